// round 15
// baseline (speedup 1.0000x reference)
#include <cuda_runtime.h>
#include <cuda_fp16.h>
#include <cstdint>
#include <math.h>

#define D_MODEL 1024
#define NH      16
#define DFF     4096
#define SEQ     2048
#define BATCH   2
#define NTOK    (BATCH*SEQ)          // 4096
#define NEG_BIG (-1e30f)

// ---------------- scratch (allocation-free rule: __device__ globals) --------
__device__ __half g_xn_h [NTOK * D_MODEL];
__device__ __half g_qkv_h[NTOK * 3 * D_MODEL];
__device__ __half g_ctx_h[NTOK * D_MODEL];
__device__ float  g_src2 [NTOK * D_MODEL];
__device__ __half g_ff1_h[NTOK * DFF];
__device__ __half g_wqkv_h[D_MODEL * 3 * D_MODEL];
__device__ __half g_wo_h  [D_MODEL * D_MODEL];
__device__ __half g_w1_h  [D_MODEL * DFF];
__device__ __half g_w2_h  [DFF * D_MODEL];

// ---------------- helpers ----------------------------------------------------
__device__ __forceinline__ void mma_f16(float c[4], uint32_t a0, uint32_t a1,
                                        uint32_t a2, uint32_t a3,
                                        uint32_t b0, uint32_t b1) {
    asm volatile(
        "mma.sync.aligned.m16n8k16.row.col.f32.f16.f16.f32 "
        "{%0,%1,%2,%3}, {%4,%5,%6,%7}, {%8,%9}, {%0,%1,%2,%3};"
        : "+f"(c[0]), "+f"(c[1]), "+f"(c[2]), "+f"(c[3])
        : "r"(a0), "r"(a1), "r"(a2), "r"(a3), "r"(b0), "r"(b1));
}
__device__ __forceinline__ void ldmx4(uint32_t& r0, uint32_t& r1,
                                      uint32_t& r2, uint32_t& r3, uint32_t addr) {
    asm volatile("ldmatrix.sync.aligned.m8n8.x4.shared.b16 {%0,%1,%2,%3}, [%4];"
                 : "=r"(r0), "=r"(r1), "=r"(r2), "=r"(r3) : "r"(addr));
}
__device__ __forceinline__ void ldmx4t(uint32_t& r0, uint32_t& r1,
                                       uint32_t& r2, uint32_t& r3, uint32_t addr) {
    asm volatile("ldmatrix.sync.aligned.m8n8.x4.trans.shared.b16 {%0,%1,%2,%3}, [%4];"
                 : "=r"(r0), "=r"(r1), "=r"(r2), "=r"(r3) : "r"(addr));
}
__device__ __forceinline__ uint32_t smem_u32(const void* p) {
    uint32_t a;
    asm("{ .reg .u64 t; cvta.to.shared.u64 t, %1; cvt.u32.u64 %0, t; }"
        : "=r"(a) : "l"(p));
    return a;
}
__device__ __forceinline__ void cp_async16(uint32_t dst, const void* src) {
    asm volatile("cp.async.cg.shared.global [%0], [%1], 16;"
                 :: "r"(dst), "l"(src) : "memory");
}
__device__ __forceinline__ void cp_commit() {
    asm volatile("cp.async.commit_group;" ::: "memory");
}
__device__ __forceinline__ uint32_t h2bits(float a, float b) {
    __half2 h = __floats2half2_rn(a, b);
    return *(uint32_t*)&h;
}
__device__ __forceinline__ float ex2(float x) {
    float y;
    asm("ex2.approx.ftz.f32 %0, %1;" : "=f"(y) : "f"(x));
    return y;
}

// ---------------- fused fp32 -> fp16 weight convert (single launch) ---------
__global__ __launch_bounds__(256) void cvt_all_kernel(
    const float* __restrict__ wqkv, const float* __restrict__ wo,
    const float* __restrict__ w1,   const float* __restrict__ w2,
    __half* __restrict__ wqkvh, __half* __restrict__ woh,
    __half* __restrict__ w1h,   __half* __restrict__ w2h)
{
    const int i = blockIdx.x * 256 + threadIdx.x;
    const float* src; __half* dst; int off;
    if      (i <  786432) { src = wqkv; dst = wqkvh; off = i; }
    else if (i < 1048576) { src = wo;   dst = woh;   off = i -  786432; }
    else if (i < 2097152) { src = w1;   dst = w1h;   off = i - 1048576; }
    else                  { src = w2;   dst = w2h;   off = i - 2097152; }
    float4 v = *(const float4*)&src[off * 4];
    *(__half2*)&dst[off * 4]     = __floats2half2_rn(v.x, v.y);
    *(__half2*)&dst[off * 4 + 2] = __floats2half2_rn(v.z, v.w);
}

// ---------------- LayerNorm (fp32 in, fp16 out) ------------------------------
__global__ __launch_bounds__(256) void ln_kernel(
    const float* __restrict__ x, const float* __restrict__ w,
    const float* __restrict__ b, __half* __restrict__ y)
{
    const int row = blockIdx.x;
    const int tid = threadIdx.x;
    const float* xr = x + (size_t)row * D_MODEL;

    float4 v = *(const float4*)&xr[tid * 4];
    float s  = v.x + v.y + v.z + v.w;
    float ss = v.x*v.x + v.y*v.y + v.z*v.z + v.w*v.w;
    #pragma unroll
    for (int o = 16; o > 0; o >>= 1) {
        s  += __shfl_xor_sync(0xffffffffu, s,  o);
        ss += __shfl_xor_sync(0xffffffffu, ss, o);
    }
    __shared__ float rs[8], rss[8];
    if ((tid & 31) == 0) { rs[tid >> 5] = s; rss[tid >> 5] = ss; }
    __syncthreads();
    float ts = 0.f, tss = 0.f;
    #pragma unroll
    for (int i = 0; i < 8; i++) { ts += rs[i]; tss += rss[i]; }

    const float mu  = ts * (1.0f / D_MODEL);
    const float var = fmaxf(tss * (1.0f / D_MODEL) - mu * mu, 0.0f);
    const float inv = rsqrtf(var + 1e-5f);

    float4 wv = *(const float4*)&w[tid * 4];
    float4 bv = *(const float4*)&b[tid * 4];
    __half* yr = y + (size_t)row * D_MODEL + tid * 4;
    *(__half2*)&yr[0] = __floats2half2_rn((v.x - mu) * inv * wv.x + bv.x,
                                          (v.y - mu) * inv * wv.y + bv.y);
    *(__half2*)&yr[2] = __floats2half2_rn((v.z - mu) * inv * wv.z + bv.z,
                                          (v.w - mu) * inv * wv.w + bv.w);
}

// ---------------- fp16 mma.sync GEMM: 128x128 tile, 4 warps (64x64), BK=32 --
// R6's exact smem layout/pipeline (4-stage, 18944 B/stage), but 128 threads:
// each warp owns a 64x64 output tile -> 8 LDSM feed 32 MMAs per k16 step.
// 3 CTAs/SM (12 warps in 3 independent barrier domains).
#define SA 40      // A_s row stride in halves (80 B)
#define SB 136     // B_s row stride in halves (272 B)
#define ABYTES (128 * SA * 2)          // 10240
#define BBYTES (32 * SB * 2)           // 8704
#define STAGE_BYTES (ABYTES + BBYTES)  // 18944
#define STAGES 4
#define GEMM_SMEM (STAGES * STAGE_BYTES)   // 75776

__device__ __forceinline__ void gemm_load_stage_h(
    const __half* __restrict__ A, const __half* __restrict__ B,
    int N, int K, int bm, int bn, int k0, uint32_t sA, uint32_t sB, int tid)
{
    // A: 128 rows x 32 halves = 512 16B chunks (4 per row), 4 per thread
    #pragma unroll
    for (int it = 0; it < 4; it++) {
        const int idx = tid + it * 128;
        const int r = idx >> 2, c16 = idx & 3;
        cp_async16(sA + (uint32_t)(r * 80 + c16 * 16),
                   &A[(size_t)(bm + r) * K + k0 + c16 * 8]);
    }
    // B: 32 rows x 128 halves = 512 16B chunks (16 per row), 4 per thread
    #pragma unroll
    for (int it = 0; it < 4; it++) {
        const int idx = tid + it * 128;
        const int k = idx >> 4, c16 = idx & 15;
        cp_async16(sB + (uint32_t)(k * 272 + c16 * 16),
                   &B[(size_t)(k0 + k) * N + bn + c16 * 8]);
    }
}

__global__ __launch_bounds__(128, 3) void gemm_h(
    const __half* __restrict__ A, const __half* __restrict__ B,
    const float* __restrict__ bias, const float* __restrict__ res,
    float* __restrict__ Cf, __half* __restrict__ Ch,
    int M, int N, int K, int relu)
{
    extern __shared__ __align__(16) unsigned short sm_h[];

    const int tid  = threadIdx.x;
    const int wid  = tid >> 5;
    const int lane = tid & 31;
    const int gid  = lane >> 2;
    const int tig  = lane & 3;
    const int wm   = (wid >> 1) * 64;
    const int wn   = (wid & 1) * 64;
    const int bm   = blockIdx.y * 128;
    const int bn   = blockIdx.x * 128;

    const uint32_t smem_base = smem_u32(sm_h);

    float acc[4][8][4];
    #pragma unroll
    for (int mt = 0; mt < 4; mt++)
        #pragma unroll
        for (int nt = 0; nt < 8; nt++)
            #pragma unroll
            for (int r = 0; r < 4; r++) acc[mt][nt][r] = 0.f;

    const int KC = K >> 5;           // BK = 32

    #pragma unroll
    for (int s = 0; s < 3; s++) {
        const uint32_t st = smem_base + (uint32_t)s * STAGE_BYTES;
        gemm_load_stage_h(A, B, N, K, bm, bn, s * 32, st, st + ABYTES, tid);
        cp_commit();
    }

    const int a_row  = lane & 15;
    const int a_col8 = 8 * (lane >> 4);
    const int b_krow = (lane & 7) + 8 * ((lane >> 3) & 1);
    const int b_col8 = 8 * (lane >> 4);

    int stage = 0;
    for (int kc = 0; kc < KC; kc++) {
        if      (kc + 2 < KC) asm volatile("cp.async.wait_group 2;" ::: "memory");
        else if (kc + 1 < KC) asm volatile("cp.async.wait_group 1;" ::: "memory");
        else                  asm volatile("cp.async.wait_group 0;" ::: "memory");
        __syncthreads();

        const uint32_t aBase = smem_base + (uint32_t)stage * STAGE_BYTES;
        const uint32_t bBase = aBase + ABYTES;

        #pragma unroll
        for (int ks = 0; ks < 2; ks++) {
            const int kk = ks * 16;
            uint32_t a[4][4];
            #pragma unroll
            for (int mt = 0; mt < 4; mt++)
                ldmx4(a[mt][0], a[mt][1], a[mt][2], a[mt][3],
                      aBase + (uint32_t)(((wm + mt * 16 + a_row) * SA
                                          + kk + a_col8) * 2));
            uint32_t bf[8][2];
            #pragma unroll
            for (int nb = 0; nb < 4; nb++) {
                uint32_t r0, r1, r2, r3;
                ldmx4t(r0, r1, r2, r3,
                       bBase + (uint32_t)(((kk + b_krow) * SB
                                           + wn + nb * 16 + b_col8) * 2));
                bf[nb * 2][0] = r0;     bf[nb * 2][1] = r1;
                bf[nb * 2 + 1][0] = r2; bf[nb * 2 + 1][1] = r3;
            }
            #pragma unroll
            for (int mt = 0; mt < 4; mt++)
                #pragma unroll
                for (int nt = 0; nt < 8; nt++)
                    mma_f16(acc[mt][nt], a[mt][0], a[mt][1], a[mt][2], a[mt][3],
                            bf[nt][0], bf[nt][1]);
        }

        if (kc + 3 < KC) {
            const int ns = (stage + 3) & 3;
            const uint32_t st = smem_base + (uint32_t)ns * STAGE_BYTES;
            gemm_load_stage_h(A, B, N, K, bm, bn, (kc + 3) * 32,
                              st, st + ABYTES, tid);
            cp_commit();
        } else {
            cp_commit();
        }
        stage = (stage + 1) & 3;
    }

    #pragma unroll
    for (int mt = 0; mt < 4; mt++) {
        #pragma unroll
        for (int r2 = 0; r2 < 2; r2++) {
            const int m = bm + wm + mt * 16 + gid + r2 * 8;
            #pragma unroll
            for (int nt = 0; nt < 8; nt++) {
                const int n = bn + wn + nt * 8 + tig * 2;
                float2 bv = *(const float2*)&bias[n];
                float ox = acc[mt][nt][r2 * 2 + 0] + bv.x;
                float oy = acc[mt][nt][r2 * 2 + 1] + bv.y;
                if (relu) { ox = fmaxf(ox, 0.f); oy = fmaxf(oy, 0.f); }
                if (res) {
                    float2 rv = *(const float2*)&res[(size_t)m * N + n];
                    ox += rv.x; oy += rv.y;
                }
                if (Ch) {
                    *(__half2*)&Ch[(size_t)m * N + n] = __floats2half2_rn(ox, oy);
                } else {
                    float2 o = { ox, oy };
                    *(float2*)&Cf[(size_t)m * N + n] = o;
                }
            }
        }
    }
}

// ---------------- fp16 flash attention: 64-q tiles, 4 CTAs/SM (R14) ---------
#define SK 72   // smem row stride in halves
#define SKIP_B 20.0f
#define SKIP_MARGIN 26.0f

__global__ __launch_bounds__(128, 4) void attn_h(
    const __half* __restrict__ qkv, __half* __restrict__ ctx)
{
    __shared__ __align__(16) __half Kh[2][64 * SK];
    __shared__ __align__(16) __half Vh[2][64 * SK];

    const int qt = (int)gridDim.x - 1 - (int)blockIdx.x;   // LPT: longest first
    const int h = blockIdx.y, b = blockIdx.z;
    const int tid  = threadIdx.x;
    const int w    = tid >> 5;
    const int lane = tid & 31;
    const int gid  = lane >> 2;
    const int tig  = lane & 3;
    const int wm   = w * 16;
    const int q_base = qt * 64;
    const size_t tok0 = (size_t)b * SEQ;
    const float LOG2E = 1.4426950408889634f;
    const float sc = 0.125f * LOG2E;                 // scale * log2(e)
    const float sl = -exp2f(-(float)h) * LOG2E;      // slope * log2(e)

    const uint32_t kB0 = smem_u32(&Kh[0][0]);
    const uint32_t kB1 = smem_u32(&Kh[1][0]);
    const uint32_t vB0 = smem_u32(&Vh[0][0]);
    const uint32_t vB1 = smem_u32(&Vh[1][0]);

    uint32_t qa[4][4];
    {
        const __half* q0 = &qkv[(tok0 + q_base + wm + gid    ) * 3072 + h * 64];
        const __half* q1 = &qkv[(tok0 + q_base + wm + gid + 8) * 3072 + h * 64];
        #pragma unroll
        for (int ko = 0; ko < 4; ko++) {
            qa[ko][0] = *(const uint32_t*)&q0[ko * 16 + 2 * tig];
            qa[ko][1] = *(const uint32_t*)&q1[ko * 16 + 2 * tig];
            qa[ko][2] = *(const uint32_t*)&q0[ko * 16 + 8 + 2 * tig];
            qa[ko][3] = *(const uint32_t*)&q1[ko * 16 + 8 + 2 * tig];
        }
    }

    float m_run[2] = {NEG_BIG, NEG_BIG};
    float l_run[2] = {0.f, 0.f};
    float oa[8][4];
    #pragma unroll
    for (int nt = 0; nt < 8; nt++)
        #pragma unroll
        for (int r = 0; r < 4; r++) oa[nt][r] = 0.f;

    const int i0 = q_base + wm + gid;
    const int i1 = i0 + 8;

    const int m_row  = lane & 15;
    const int m_col8 = 8 * (lane >> 4);

    const int nkt = qt + 1;

    // prologue: async-load tile 0 into buffer 0 (128 threads, 4 passes)
    {
        for (int i = tid; i < 512; i += 128) {
            const int r = i >> 3, c8 = (i & 7) * 8;
            const __half* kb = &qkv[(tok0 + r) * 3072 + 1024 + h * 64 + c8];
            const uint32_t off = (uint32_t)((r * SK + c8) * 2);
            cp_async16(kB0 + off, kb);
            cp_async16(vB0 + off, kb + 1024);
        }
        cp_commit();
    }

    for (int kt = 0; kt < nkt; kt++) {
        const int k_base = kt * 64;
        const int buf = kt & 1;
        const uint32_t kBase = buf ? kB1 : kB0;
        const uint32_t vBase = buf ? vB1 : vB0;

        // warp-uniform need for tile kt (both terms monotone-decreasing in kt)
        bool need = (k_base <= q_base + wm + 15);
        if (need && kt > 0) {
            const float vmax = SKIP_B + (float)k_base * sl;
            need = (vmax >= fminf(m_run[0], m_run[1]) - SKIP_MARGIN);
        }
        // loop-top barrier: CTA-wide break vote AND separator between the
        // previous iteration's compute and this iteration's buffer overwrite
        if (!__syncthreads_or(need ? 1 : 0)) break;
        const bool live = __any_sync(0xffffffffu, need);

        // issue loads for tile kt+1 into the other buffer
        if (kt + 1 < nkt) {
            const uint32_t kN = buf ? kB0 : kB1;
            const uint32_t vN = buf ? vB0 : vB1;
            const int kb2 = (kt + 1) * 64;
            for (int i = tid; i < 512; i += 128) {
                const int r = i >> 3, c8 = (i & 7) * 8;
                const __half* kb = &qkv[(tok0 + kb2 + r) * 3072 + 1024 + h * 64 + c8];
                const uint32_t off = (uint32_t)((r * SK + c8) * 2);
                cp_async16(kN + off, kb);
                cp_async16(vN + off, kb + 1024);
            }
            cp_commit();
            asm volatile("cp.async.wait_group 1;" ::: "memory");
        } else {
            asm volatile("cp.async.wait_group 0;" ::: "memory");
        }
        __syncthreads();

        if (live) {
            float sf[8][4];
            #pragma unroll
            for (int nt = 0; nt < 8; nt++)
                #pragma unroll
                for (int r = 0; r < 4; r++) sf[nt][r] = 0.f;
            #pragma unroll
            for (int ko = 0; ko < 4; ko++) {
                #pragma unroll
                for (int nb = 0; nb < 4; nb++) {
                    uint32_t r0, r1, r2, r3;
                    ldmx4(r0, r1, r2, r3,
                          kBase + (uint32_t)(((nb * 16 + m_row) * SK
                                              + ko * 16 + m_col8) * 2));
                    mma_f16(sf[2 * nb    ], qa[ko][0], qa[ko][1], qa[ko][2], qa[ko][3], r0, r2);
                    mma_f16(sf[2 * nb + 1], qa[ko][0], qa[ko][1], qa[ko][2], qa[ko][3], r1, r3);
                }
            }

            const bool maskt = (k_base + 63 > q_base + wm);
            float mx0 = NEG_BIG, mx1 = NEG_BIG;
            #pragma unroll
            for (int nt = 0; nt < 8; nt++) {
                const int j0 = k_base + nt * 8 + tig * 2;
                const float bj0 = (float)j0 * sl;
                const float bj1 = bj0 + sl;
                float v0 = fmaf(sf[nt][0], sc, bj0);
                float v1 = fmaf(sf[nt][1], sc, bj1);
                float v2 = fmaf(sf[nt][2], sc, bj0);
                float v3 = fmaf(sf[nt][3], sc, bj1);
                if (maskt) {
                    if (j0     > i0) v0 = NEG_BIG;
                    if (j0 + 1 > i0) v1 = NEG_BIG;
                    if (j0     > i1) v2 = NEG_BIG;
                    if (j0 + 1 > i1) v3 = NEG_BIG;
                }
                sf[nt][0] = v0; sf[nt][1] = v1; sf[nt][2] = v2; sf[nt][3] = v3;
                mx0 = fmaxf(mx0, fmaxf(v0, v1));
                mx1 = fmaxf(mx1, fmaxf(v2, v3));
            }
            mx0 = fmaxf(mx0, __shfl_xor_sync(0xffffffffu, mx0, 1));
            mx0 = fmaxf(mx0, __shfl_xor_sync(0xffffffffu, mx0, 2));
            mx1 = fmaxf(mx1, __shfl_xor_sync(0xffffffffu, mx1, 1));
            mx1 = fmaxf(mx1, __shfl_xor_sync(0xffffffffu, mx1, 2));

            const float mn0 = fmaxf(m_run[0], mx0);
            const float mn1 = fmaxf(m_run[1], mx1);
            const float corr0 = ex2(m_run[0] - mn0);
            const float corr1 = ex2(m_run[1] - mn1);
            float s0 = 0.f, s1 = 0.f;
            uint32_t pH[8][2];
            #pragma unroll
            for (int nt = 0; nt < 8; nt++) {
                const float p0 = ex2(sf[nt][0] - mn0);
                const float p1 = ex2(sf[nt][1] - mn0);
                const float p2 = ex2(sf[nt][2] - mn1);
                const float p3 = ex2(sf[nt][3] - mn1);
                s0 += p0 + p1; s1 += p2 + p3;
                pH[nt][0] = h2bits(p0, p1);
                pH[nt][1] = h2bits(p2, p3);
            }
            s0 += __shfl_xor_sync(0xffffffffu, s0, 1);
            s0 += __shfl_xor_sync(0xffffffffu, s0, 2);
            s1 += __shfl_xor_sync(0xffffffffu, s1, 1);
            s1 += __shfl_xor_sync(0xffffffffu, s1, 2);
            l_run[0] = l_run[0] * corr0 + s0;
            l_run[1] = l_run[1] * corr1 + s1;
            m_run[0] = mn0; m_run[1] = mn1;
            #pragma unroll
            for (int nt = 0; nt < 8; nt++) {
                oa[nt][0] *= corr0; oa[nt][1] *= corr0;
                oa[nt][2] *= corr1; oa[nt][3] *= corr1;
            }

            #pragma unroll
            for (int ko2 = 0; ko2 < 4; ko2++) {
                const uint32_t pa0 = pH[2 * ko2][0];
                const uint32_t pa1 = pH[2 * ko2][1];
                const uint32_t pa2 = pH[2 * ko2 + 1][0];
                const uint32_t pa3 = pH[2 * ko2 + 1][1];
                #pragma unroll
                for (int vb = 0; vb < 4; vb++) {
                    uint32_t r0, r1, r2, r3;
                    ldmx4t(r0, r1, r2, r3,
                           vBase + (uint32_t)(((ko2 * 16 + (lane & 7)
                                                + 8 * ((lane >> 3) & 1)) * SK
                                               + vb * 16 + m_col8) * 2));
                    mma_f16(oa[2 * vb    ], pa0, pa1, pa2, pa3, r0, r1);
                    mma_f16(oa[2 * vb + 1], pa0, pa1, pa2, pa3, r2, r3);
                }
            }
        }
        // no trailing barrier — loop-top __syncthreads_or separates compute
        // from the next iteration's buffer overwrite
    }

    const float inv0 = 1.0f / l_run[0];
    const float inv1 = 1.0f / l_run[1];
    __half* c0 = &ctx[(tok0 + q_base + wm + gid    ) * D_MODEL + h * 64];
    __half* c1 = &ctx[(tok0 + q_base + wm + gid + 8) * D_MODEL + h * 64];
    #pragma unroll
    for (int nt = 0; nt < 8; nt++) {
        *(__half2*)&c0[nt * 8 + tig * 2] =
            __floats2half2_rn(oa[nt][0] * inv0, oa[nt][1] * inv0);
        *(__half2*)&c1[nt * 8 + tig * 2] =
            __floats2half2_rn(oa[nt][2] * inv1, oa[nt][3] * inv1);
    }
}

// ---------------- launch ----------------------------------------------------
extern "C" void kernel_launch(void* const* d_in, const int* in_sizes, int n_in,
                              void* d_out, int out_size)
{
    const float* src  = (const float*)d_in[0];
    const float* ln1w = (const float*)d_in[1];
    const float* ln1b = (const float*)d_in[2];
    const float* wqkv = (const float*)d_in[3];
    const float* bqkv = (const float*)d_in[4];
    const float* wo   = (const float*)d_in[5];
    const float* bo   = (const float*)d_in[6];
    const float* ln2w = (const float*)d_in[7];
    const float* ln2b = (const float*)d_in[8];
    const float* w1   = (const float*)d_in[9];
    const float* b1   = (const float*)d_in[10];
    const float* w2   = (const float*)d_in[11];
    const float* b2   = (const float*)d_in[12];
    float* out = (float*)d_out;

    __half *xn, *qkvh, *ctx, *ff1, *wqkvh, *woh, *w1h, *w2h;
    float *src2;
    cudaGetSymbolAddress((void**)&xn,    g_xn_h);
    cudaGetSymbolAddress((void**)&qkvh,  g_qkv_h);
    cudaGetSymbolAddress((void**)&ctx,   g_ctx_h);
    cudaGetSymbolAddress((void**)&src2,  g_src2);
    cudaGetSymbolAddress((void**)&ff1,   g_ff1_h);
    cudaGetSymbolAddress((void**)&wqkvh, g_wqkv_h);
    cudaGetSymbolAddress((void**)&woh,   g_wo_h);
    cudaGetSymbolAddress((void**)&w1h,   g_w1_h);
    cudaGetSymbolAddress((void**)&w2h,   g_w2_h);

    cudaFuncSetAttribute(gemm_h,
                         cudaFuncAttributeMaxDynamicSharedMemorySize, GEMM_SMEM);

    // fused weight conversion (one launch)
    cvt_all_kernel<<<3145728 / 256, 256>>>(
        wqkv, wo, w1, w2, wqkvh, woh, w1h, w2h);

    // 1) LN1 -> fp16
    ln_kernel<<<NTOK, 256>>>(src, ln1w, ln1b, xn);
    // 2) QKV projection -> fp16 qkv
    gemm_h<<<dim3(3 * D_MODEL / 128, NTOK / 128), 128, GEMM_SMEM>>>(
        xn, wqkvh, bqkv, nullptr, nullptr, qkvh, NTOK, 3 * D_MODEL, D_MODEL, 0);
    // 3) attention (64-row q tiles, 4 CTAs/SM) -> fp16 ctx
    attn_h<<<dim3(SEQ / 64, NH, BATCH), 128>>>(qkvh, ctx);
    // 4) output projection + residual -> fp32 src2
    gemm_h<<<dim3(D_MODEL / 128, NTOK / 128), 128, GEMM_SMEM>>>(
        ctx, woh, bo, src, src2, nullptr, NTOK, D_MODEL, D_MODEL, 0);
    // 5) LN2 -> fp16
    ln_kernel<<<NTOK, 256>>>(src2, ln2w, ln2b, xn);
    // 6) FFN up + ReLU -> fp16 ff1
    gemm_h<<<dim3(DFF / 128, NTOK / 128), 128, GEMM_SMEM>>>(
        xn, w1h, b1, nullptr, nullptr, ff1, NTOK, DFF, D_MODEL, 1);
    // 7) FFN down + residual -> fp32 out
    gemm_h<<<dim3(D_MODEL / 128, NTOK / 128), 128, GEMM_SMEM>>>(
        ff1, w2h, b2, src2, out, nullptr, NTOK, D_MODEL, DFF, 0);
}

// round 16
// speedup vs baseline: 1.0798x; 1.0798x over previous
#include <cuda_runtime.h>
#include <cuda_fp16.h>
#include <cstdint>
#include <math.h>

#define D_MODEL 1024
#define NH      16
#define DFF     4096
#define SEQ     2048
#define BATCH   2
#define NTOK    (BATCH*SEQ)          // 4096
#define NEG_BIG (-1e30f)

// ---------------- scratch (allocation-free rule: __device__ globals) --------
__device__ __half g_xn_h [NTOK * D_MODEL];
__device__ __half g_qkv_h[NTOK * 3 * D_MODEL];
__device__ __half g_ctx_h[NTOK * D_MODEL];
__device__ float  g_src2 [NTOK * D_MODEL];
__device__ __half g_ff1_h[NTOK * DFF];
__device__ __half g_wqkv_h[D_MODEL * 3 * D_MODEL];
__device__ __half g_wo_h  [D_MODEL * D_MODEL];
__device__ __half g_w1_h  [D_MODEL * DFF];
__device__ __half g_w2_h  [DFF * D_MODEL];

// ---------------- helpers ----------------------------------------------------
__device__ __forceinline__ void mma_f16(float c[4], uint32_t a0, uint32_t a1,
                                        uint32_t a2, uint32_t a3,
                                        uint32_t b0, uint32_t b1) {
    asm volatile(
        "mma.sync.aligned.m16n8k16.row.col.f32.f16.f16.f32 "
        "{%0,%1,%2,%3}, {%4,%5,%6,%7}, {%8,%9}, {%0,%1,%2,%3};"
        : "+f"(c[0]), "+f"(c[1]), "+f"(c[2]), "+f"(c[3])
        : "r"(a0), "r"(a1), "r"(a2), "r"(a3), "r"(b0), "r"(b1));
}
__device__ __forceinline__ void ldmx4(uint32_t& r0, uint32_t& r1,
                                      uint32_t& r2, uint32_t& r3, uint32_t addr) {
    asm volatile("ldmatrix.sync.aligned.m8n8.x4.shared.b16 {%0,%1,%2,%3}, [%4];"
                 : "=r"(r0), "=r"(r1), "=r"(r2), "=r"(r3) : "r"(addr));
}
__device__ __forceinline__ void ldmx4t(uint32_t& r0, uint32_t& r1,
                                       uint32_t& r2, uint32_t& r3, uint32_t addr) {
    asm volatile("ldmatrix.sync.aligned.m8n8.x4.trans.shared.b16 {%0,%1,%2,%3}, [%4];"
                 : "=r"(r0), "=r"(r1), "=r"(r2), "=r"(r3) : "r"(addr));
}
__device__ __forceinline__ uint32_t smem_u32(const void* p) {
    uint32_t a;
    asm("{ .reg .u64 t; cvta.to.shared.u64 t, %1; cvt.u32.u64 %0, t; }"
        : "=r"(a) : "l"(p));
    return a;
}
__device__ __forceinline__ void cp_async16(uint32_t dst, const void* src) {
    asm volatile("cp.async.cg.shared.global [%0], [%1], 16;"
                 :: "r"(dst), "l"(src) : "memory");
}
__device__ __forceinline__ void cp_commit() {
    asm volatile("cp.async.commit_group;" ::: "memory");
}
__device__ __forceinline__ uint32_t h2bits(float a, float b) {
    __half2 h = __floats2half2_rn(a, b);
    return *(uint32_t*)&h;
}
__device__ __forceinline__ float ex2(float x) {
    float y;
    asm("ex2.approx.ftz.f32 %0, %1;" : "=f"(y) : "f"(x));
    return y;
}

// ---------------- fused fp32 -> fp16 weight convert (single launch) ---------
__global__ __launch_bounds__(256) void cvt_all_kernel(
    const float* __restrict__ wqkv, const float* __restrict__ wo,
    const float* __restrict__ w1,   const float* __restrict__ w2,
    __half* __restrict__ wqkvh, __half* __restrict__ woh,
    __half* __restrict__ w1h,   __half* __restrict__ w2h)
{
    const int i = blockIdx.x * 256 + threadIdx.x;
    const float* src; __half* dst; int off;
    if      (i <  786432) { src = wqkv; dst = wqkvh; off = i; }
    else if (i < 1048576) { src = wo;   dst = woh;   off = i -  786432; }
    else if (i < 2097152) { src = w1;   dst = w1h;   off = i - 1048576; }
    else                  { src = w2;   dst = w2h;   off = i - 2097152; }
    float4 v = *(const float4*)&src[off * 4];
    *(__half2*)&dst[off * 4]     = __floats2half2_rn(v.x, v.y);
    *(__half2*)&dst[off * 4 + 2] = __floats2half2_rn(v.z, v.w);
}

// ---------------- LayerNorm: warp-per-row (no barriers, no smem) ------------
// 256 threads = 8 warps = 8 rows per block; lane holds 32 elements as 8
// strided float4 (stride 128 floats -> fully coalesced). 5 shfl reductions.
__global__ __launch_bounds__(256) void ln_kernel(
    const float* __restrict__ x, const float* __restrict__ w,
    const float* __restrict__ b, __half* __restrict__ y)
{
    const int row  = blockIdx.x * 8 + (threadIdx.x >> 5);
    const int lane = threadIdx.x & 31;
    const float* xr = x + (size_t)row * D_MODEL;

    float4 v[8];
    float s = 0.f, ss = 0.f;
    #pragma unroll
    for (int k = 0; k < 8; k++) {
        v[k] = *(const float4*)&xr[k * 128 + lane * 4];
        s  += v[k].x + v[k].y + v[k].z + v[k].w;
        ss += v[k].x*v[k].x + v[k].y*v[k].y + v[k].z*v[k].z + v[k].w*v[k].w;
    }
    #pragma unroll
    for (int o = 16; o > 0; o >>= 1) {
        s  += __shfl_xor_sync(0xffffffffu, s,  o);
        ss += __shfl_xor_sync(0xffffffffu, ss, o);
    }

    const float mu  = s * (1.0f / D_MODEL);
    const float var = fmaxf(ss * (1.0f / D_MODEL) - mu * mu, 0.0f);
    const float inv = rsqrtf(var + 1e-5f);

    __half* yr = y + (size_t)row * D_MODEL;
    #pragma unroll
    for (int k = 0; k < 8; k++) {
        const int c = k * 128 + lane * 4;
        float4 wv = *(const float4*)&w[c];
        float4 bv = *(const float4*)&b[c];
        *(__half2*)&yr[c]     = __floats2half2_rn((v[k].x - mu) * inv * wv.x + bv.x,
                                                  (v[k].y - mu) * inv * wv.y + bv.y);
        *(__half2*)&yr[c + 2] = __floats2half2_rn((v[k].z - mu) * inv * wv.z + bv.z,
                                                  (v[k].w - mu) * inv * wv.w + bv.w);
    }
}

// ---------------- fp16 mma.sync GEMM: 128x128 tile, BK=64, 3-stage (R12) ----
#define SA 72      // A_s row stride in halves (144 B = 9 x 16B segs, odd -> cf)
#define SB 136     // B_s row stride in halves (272 B)
#define ABYTES (128 * SA * 2)          // 18432
#define BBYTES (64 * SB * 2)           // 17408
#define STAGE_BYTES (ABYTES + BBYTES)  // 35840
#define STAGES 3
#define GEMM_SMEM (STAGES * STAGE_BYTES)   // 107520

__device__ __forceinline__ void gemm_load_stage_h(
    const __half* __restrict__ A, const __half* __restrict__ B,
    int N, int K, int bm, int bn, int k0, uint32_t sA, uint32_t sB, int tid)
{
    #pragma unroll
    for (int it = 0; it < 4; it++) {
        const int idx = tid + it * 256;
        const int r = idx >> 3, c16 = idx & 7;
        cp_async16(sA + (uint32_t)(r * 144 + c16 * 16),
                   &A[(size_t)(bm + r) * K + k0 + c16 * 8]);
    }
    #pragma unroll
    for (int it = 0; it < 4; it++) {
        const int idx = tid + it * 256;
        const int k = idx >> 4, c16 = idx & 15;
        cp_async16(sB + (uint32_t)(k * 272 + c16 * 16),
                   &B[(size_t)(k0 + k) * N + bn + c16 * 8]);
    }
}

__global__ __launch_bounds__(256, 2) void gemm_h(
    const __half* __restrict__ A, const __half* __restrict__ B,
    const float* __restrict__ bias, const float* __restrict__ res,
    float* __restrict__ Cf, __half* __restrict__ Ch,
    int M, int N, int K, int relu)
{
    extern __shared__ __align__(16) unsigned short sm_h[];

    const int tid  = threadIdx.x;
    const int wid  = tid >> 5;
    const int lane = tid & 31;
    const int gid  = lane >> 2;
    const int tig  = lane & 3;
    const int wm   = (wid >> 2) * 64;
    const int wn   = (wid & 3) * 32;
    const int bm   = blockIdx.y * 128;
    const int bn   = blockIdx.x * 128;

    const uint32_t smem_base = smem_u32(sm_h);

    float acc[4][4][4];
    #pragma unroll
    for (int mt = 0; mt < 4; mt++)
        #pragma unroll
        for (int nt = 0; nt < 4; nt++)
            #pragma unroll
            for (int r = 0; r < 4; r++) acc[mt][nt][r] = 0.f;

    const int KC = K >> 6;           // BK = 64

    #pragma unroll
    for (int s = 0; s < 2; s++) {
        const uint32_t st = smem_base + (uint32_t)s * STAGE_BYTES;
        gemm_load_stage_h(A, B, N, K, bm, bn, s * 64, st, st + ABYTES, tid);
        cp_commit();
    }

    const int a_row  = lane & 15;
    const int a_col8 = 8 * (lane >> 4);
    const int b_krow = (lane & 7) + 8 * ((lane >> 3) & 1);
    const int b_col8 = 8 * (lane >> 4);

    int stage = 0;
    for (int kc = 0; kc < KC; kc++) {
        if (kc + 1 < KC) asm volatile("cp.async.wait_group 1;" ::: "memory");
        else             asm volatile("cp.async.wait_group 0;" ::: "memory");
        __syncthreads();

        const uint32_t aBase = smem_base + (uint32_t)stage * STAGE_BYTES;
        const uint32_t bBase = aBase + ABYTES;

        #pragma unroll
        for (int ks = 0; ks < 4; ks++) {
            const int kk = ks * 16;
            uint32_t a[4][4];
            #pragma unroll
            for (int mt = 0; mt < 4; mt++)
                ldmx4(a[mt][0], a[mt][1], a[mt][2], a[mt][3],
                      aBase + (uint32_t)(((wm + mt * 16 + a_row) * SA
                                          + kk + a_col8) * 2));
            uint32_t bf[4][2];
            #pragma unroll
            for (int np = 0; np < 2; np++) {
                uint32_t r0, r1, r2, r3;
                ldmx4t(r0, r1, r2, r3,
                       bBase + (uint32_t)(((kk + b_krow) * SB
                                           + wn + np * 16 + b_col8) * 2));
                bf[np * 2][0] = r0;     bf[np * 2][1] = r1;
                bf[np * 2 + 1][0] = r2; bf[np * 2 + 1][1] = r3;
            }
            #pragma unroll
            for (int mt = 0; mt < 4; mt++)
                #pragma unroll
                for (int nt = 0; nt < 4; nt++)
                    mma_f16(acc[mt][nt], a[mt][0], a[mt][1], a[mt][2], a[mt][3],
                            bf[nt][0], bf[nt][1]);
        }

        if (kc + 2 < KC) {
            const int ns = (stage + 2 >= STAGES) ? stage + 2 - STAGES : stage + 2;
            const uint32_t st = smem_base + (uint32_t)ns * STAGE_BYTES;
            gemm_load_stage_h(A, B, N, K, bm, bn, (kc + 2) * 64,
                              st, st + ABYTES, tid);
            cp_commit();
        } else {
            cp_commit();
        }
        stage = (stage + 1 == STAGES) ? 0 : stage + 1;
    }

    #pragma unroll
    for (int mt = 0; mt < 4; mt++) {
        #pragma unroll
        for (int r2 = 0; r2 < 2; r2++) {
            const int m = bm + wm + mt * 16 + gid + r2 * 8;
            #pragma unroll
            for (int nt = 0; nt < 4; nt++) {
                const int n = bn + wn + nt * 8 + tig * 2;
                float2 bv = *(const float2*)&bias[n];
                float ox = acc[mt][nt][r2 * 2 + 0] + bv.x;
                float oy = acc[mt][nt][r2 * 2 + 1] + bv.y;
                if (relu) { ox = fmaxf(ox, 0.f); oy = fmaxf(oy, 0.f); }
                if (res) {
                    float2 rv = *(const float2*)&res[(size_t)m * N + n];
                    ox += rv.x; oy += rv.y;
                }
                if (Ch) {
                    *(__half2*)&Ch[(size_t)m * N + n] = __floats2half2_rn(ox, oy);
                } else {
                    float2 o = { ox, oy };
                    *(float2*)&Cf[(size_t)m * N + n] = o;
                }
            }
        }
    }
}

// ---------------- fp16 flash attention: 64-q tiles, 4 CTAs/SM (R14) ---------
#define SK 72   // smem row stride in halves
#define SKIP_B 20.0f
#define SKIP_MARGIN 26.0f

__global__ __launch_bounds__(128, 4) void attn_h(
    const __half* __restrict__ qkv, __half* __restrict__ ctx)
{
    __shared__ __align__(16) __half Kh[2][64 * SK];
    __shared__ __align__(16) __half Vh[2][64 * SK];

    const int qt = (int)gridDim.x - 1 - (int)blockIdx.x;   // LPT: longest first
    const int h = blockIdx.y, b = blockIdx.z;
    const int tid  = threadIdx.x;
    const int w    = tid >> 5;
    const int lane = tid & 31;
    const int gid  = lane >> 2;
    const int tig  = lane & 3;
    const int wm   = w * 16;
    const int q_base = qt * 64;
    const size_t tok0 = (size_t)b * SEQ;
    const float LOG2E = 1.4426950408889634f;
    const float sc = 0.125f * LOG2E;                 // scale * log2(e)
    const float sl = -exp2f(-(float)h) * LOG2E;      // slope * log2(e)

    const uint32_t kB0 = smem_u32(&Kh[0][0]);
    const uint32_t kB1 = smem_u32(&Kh[1][0]);
    const uint32_t vB0 = smem_u32(&Vh[0][0]);
    const uint32_t vB1 = smem_u32(&Vh[1][0]);

    uint32_t qa[4][4];
    {
        const __half* q0 = &qkv[(tok0 + q_base + wm + gid    ) * 3072 + h * 64];
        const __half* q1 = &qkv[(tok0 + q_base + wm + gid + 8) * 3072 + h * 64];
        #pragma unroll
        for (int ko = 0; ko < 4; ko++) {
            qa[ko][0] = *(const uint32_t*)&q0[ko * 16 + 2 * tig];
            qa[ko][1] = *(const uint32_t*)&q1[ko * 16 + 2 * tig];
            qa[ko][2] = *(const uint32_t*)&q0[ko * 16 + 8 + 2 * tig];
            qa[ko][3] = *(const uint32_t*)&q1[ko * 16 + 8 + 2 * tig];
        }
    }

    float m_run[2] = {NEG_BIG, NEG_BIG};
    float l_run[2] = {0.f, 0.f};
    float oa[8][4];
    #pragma unroll
    for (int nt = 0; nt < 8; nt++)
        #pragma unroll
        for (int r = 0; r < 4; r++) oa[nt][r] = 0.f;

    const int i0 = q_base + wm + gid;
    const int i1 = i0 + 8;

    const int m_row  = lane & 15;
    const int m_col8 = 8 * (lane >> 4);

    const int nkt = qt + 1;

    // prologue: async-load tile 0 into buffer 0 (128 threads, 4 passes)
    {
        for (int i = tid; i < 512; i += 128) {
            const int r = i >> 3, c8 = (i & 7) * 8;
            const __half* kb = &qkv[(tok0 + r) * 3072 + 1024 + h * 64 + c8];
            const uint32_t off = (uint32_t)((r * SK + c8) * 2);
            cp_async16(kB0 + off, kb);
            cp_async16(vB0 + off, kb + 1024);
        }
        cp_commit();
    }

    for (int kt = 0; kt < nkt; kt++) {
        const int k_base = kt * 64;
        const int buf = kt & 1;
        const uint32_t kBase = buf ? kB1 : kB0;
        const uint32_t vBase = buf ? vB1 : vB0;

        // warp-uniform need for tile kt (both terms monotone-decreasing in kt)
        bool need = (k_base <= q_base + wm + 15);
        if (need && kt > 0) {
            const float vmax = SKIP_B + (float)k_base * sl;
            need = (vmax >= fminf(m_run[0], m_run[1]) - SKIP_MARGIN);
        }
        // loop-top barrier: CTA-wide break vote AND separator between the
        // previous iteration's compute and this iteration's buffer overwrite
        if (!__syncthreads_or(need ? 1 : 0)) break;
        const bool live = __any_sync(0xffffffffu, need);

        // issue loads for tile kt+1 into the other buffer
        if (kt + 1 < nkt) {
            const uint32_t kN = buf ? kB0 : kB1;
            const uint32_t vN = buf ? vB0 : vB1;
            const int kb2 = (kt + 1) * 64;
            for (int i = tid; i < 512; i += 128) {
                const int r = i >> 3, c8 = (i & 7) * 8;
                const __half* kb = &qkv[(tok0 + kb2 + r) * 3072 + 1024 + h * 64 + c8];
                const uint32_t off = (uint32_t)((r * SK + c8) * 2);
                cp_async16(kN + off, kb);
                cp_async16(vN + off, kb + 1024);
            }
            cp_commit();
            asm volatile("cp.async.wait_group 1;" ::: "memory");
        } else {
            asm volatile("cp.async.wait_group 0;" ::: "memory");
        }
        __syncthreads();

        if (live) {
            float sf[8][4];
            #pragma unroll
            for (int nt = 0; nt < 8; nt++)
                #pragma unroll
                for (int r = 0; r < 4; r++) sf[nt][r] = 0.f;
            #pragma unroll
            for (int ko = 0; ko < 4; ko++) {
                #pragma unroll
                for (int nb = 0; nb < 4; nb++) {
                    uint32_t r0, r1, r2, r3;
                    ldmx4(r0, r1, r2, r3,
                          kBase + (uint32_t)(((nb * 16 + m_row) * SK
                                              + ko * 16 + m_col8) * 2));
                    mma_f16(sf[2 * nb    ], qa[ko][0], qa[ko][1], qa[ko][2], qa[ko][3], r0, r2);
                    mma_f16(sf[2 * nb + 1], qa[ko][0], qa[ko][1], qa[ko][2], qa[ko][3], r1, r3);
                }
            }

            const bool maskt = (k_base + 63 > q_base + wm);
            float mx0 = NEG_BIG, mx1 = NEG_BIG;
            #pragma unroll
            for (int nt = 0; nt < 8; nt++) {
                const int j0 = k_base + nt * 8 + tig * 2;
                const float bj0 = (float)j0 * sl;
                const float bj1 = bj0 + sl;
                float v0 = fmaf(sf[nt][0], sc, bj0);
                float v1 = fmaf(sf[nt][1], sc, bj1);
                float v2 = fmaf(sf[nt][2], sc, bj0);
                float v3 = fmaf(sf[nt][3], sc, bj1);
                if (maskt) {
                    if (j0     > i0) v0 = NEG_BIG;
                    if (j0 + 1 > i0) v1 = NEG_BIG;
                    if (j0     > i1) v2 = NEG_BIG;
                    if (j0 + 1 > i1) v3 = NEG_BIG;
                }
                sf[nt][0] = v0; sf[nt][1] = v1; sf[nt][2] = v2; sf[nt][3] = v3;
                mx0 = fmaxf(mx0, fmaxf(v0, v1));
                mx1 = fmaxf(mx1, fmaxf(v2, v3));
            }
            mx0 = fmaxf(mx0, __shfl_xor_sync(0xffffffffu, mx0, 1));
            mx0 = fmaxf(mx0, __shfl_xor_sync(0xffffffffu, mx0, 2));
            mx1 = fmaxf(mx1, __shfl_xor_sync(0xffffffffu, mx1, 1));
            mx1 = fmaxf(mx1, __shfl_xor_sync(0xffffffffu, mx1, 2));

            const float mn0 = fmaxf(m_run[0], mx0);
            const float mn1 = fmaxf(m_run[1], mx1);
            const float corr0 = ex2(m_run[0] - mn0);
            const float corr1 = ex2(m_run[1] - mn1);
            float s0 = 0.f, s1 = 0.f;
            uint32_t pH[8][2];
            #pragma unroll
            for (int nt = 0; nt < 8; nt++) {
                const float p0 = ex2(sf[nt][0] - mn0);
                const float p1 = ex2(sf[nt][1] - mn0);
                const float p2 = ex2(sf[nt][2] - mn1);
                const float p3 = ex2(sf[nt][3] - mn1);
                s0 += p0 + p1; s1 += p2 + p3;
                pH[nt][0] = h2bits(p0, p1);
                pH[nt][1] = h2bits(p2, p3);
            }
            s0 += __shfl_xor_sync(0xffffffffu, s0, 1);
            s0 += __shfl_xor_sync(0xffffffffu, s0, 2);
            s1 += __shfl_xor_sync(0xffffffffu, s1, 1);
            s1 += __shfl_xor_sync(0xffffffffu, s1, 2);
            l_run[0] = l_run[0] * corr0 + s0;
            l_run[1] = l_run[1] * corr1 + s1;
            m_run[0] = mn0; m_run[1] = mn1;
            #pragma unroll
            for (int nt = 0; nt < 8; nt++) {
                oa[nt][0] *= corr0; oa[nt][1] *= corr0;
                oa[nt][2] *= corr1; oa[nt][3] *= corr1;
            }

            #pragma unroll
            for (int ko2 = 0; ko2 < 4; ko2++) {
                const uint32_t pa0 = pH[2 * ko2][0];
                const uint32_t pa1 = pH[2 * ko2][1];
                const uint32_t pa2 = pH[2 * ko2 + 1][0];
                const uint32_t pa3 = pH[2 * ko2 + 1][1];
                #pragma unroll
                for (int vb = 0; vb < 4; vb++) {
                    uint32_t r0, r1, r2, r3;
                    ldmx4t(r0, r1, r2, r3,
                           vBase + (uint32_t)(((ko2 * 16 + (lane & 7)
                                                + 8 * ((lane >> 3) & 1)) * SK
                                               + vb * 16 + m_col8) * 2));
                    mma_f16(oa[2 * vb    ], pa0, pa1, pa2, pa3, r0, r1);
                    mma_f16(oa[2 * vb + 1], pa0, pa1, pa2, pa3, r2, r3);
                }
            }
        }
        // no trailing barrier — loop-top __syncthreads_or separates compute
        // from the next iteration's buffer overwrite
    }

    const float inv0 = 1.0f / l_run[0];
    const float inv1 = 1.0f / l_run[1];
    __half* c0 = &ctx[(tok0 + q_base + wm + gid    ) * D_MODEL + h * 64];
    __half* c1 = &ctx[(tok0 + q_base + wm + gid + 8) * D_MODEL + h * 64];
    #pragma unroll
    for (int nt = 0; nt < 8; nt++) {
        *(__half2*)&c0[nt * 8 + tig * 2] =
            __floats2half2_rn(oa[nt][0] * inv0, oa[nt][1] * inv0);
        *(__half2*)&c1[nt * 8 + tig * 2] =
            __floats2half2_rn(oa[nt][2] * inv1, oa[nt][3] * inv1);
    }
}

// ---------------- launch ----------------------------------------------------
extern "C" void kernel_launch(void* const* d_in, const int* in_sizes, int n_in,
                              void* d_out, int out_size)
{
    const float* src  = (const float*)d_in[0];
    const float* ln1w = (const float*)d_in[1];
    const float* ln1b = (const float*)d_in[2];
    const float* wqkv = (const float*)d_in[3];
    const float* bqkv = (const float*)d_in[4];
    const float* wo   = (const float*)d_in[5];
    const float* bo   = (const float*)d_in[6];
    const float* ln2w = (const float*)d_in[7];
    const float* ln2b = (const float*)d_in[8];
    const float* w1   = (const float*)d_in[9];
    const float* b1   = (const float*)d_in[10];
    const float* w2   = (const float*)d_in[11];
    const float* b2   = (const float*)d_in[12];
    float* out = (float*)d_out;

    __half *xn, *qkvh, *ctx, *ff1, *wqkvh, *woh, *w1h, *w2h;
    float *src2;
    cudaGetSymbolAddress((void**)&xn,    g_xn_h);
    cudaGetSymbolAddress((void**)&qkvh,  g_qkv_h);
    cudaGetSymbolAddress((void**)&ctx,   g_ctx_h);
    cudaGetSymbolAddress((void**)&src2,  g_src2);
    cudaGetSymbolAddress((void**)&ff1,   g_ff1_h);
    cudaGetSymbolAddress((void**)&wqkvh, g_wqkv_h);
    cudaGetSymbolAddress((void**)&woh,   g_wo_h);
    cudaGetSymbolAddress((void**)&w1h,   g_w1_h);
    cudaGetSymbolAddress((void**)&w2h,   g_w2_h);

    cudaFuncSetAttribute(gemm_h,
                         cudaFuncAttributeMaxDynamicSharedMemorySize, GEMM_SMEM);

    // fused weight conversion (one launch)
    cvt_all_kernel<<<3145728 / 256, 256>>>(
        wqkv, wo, w1, w2, wqkvh, woh, w1h, w2h);

    // 1) LN1 -> fp16 (warp-per-row)
    ln_kernel<<<NTOK / 8, 256>>>(src, ln1w, ln1b, xn);
    // 2) QKV projection -> fp16 qkv
    gemm_h<<<dim3(3 * D_MODEL / 128, NTOK / 128), 256, GEMM_SMEM>>>(
        xn, wqkvh, bqkv, nullptr, nullptr, qkvh, NTOK, 3 * D_MODEL, D_MODEL, 0);
    // 3) attention (64-row q tiles, 4 CTAs/SM) -> fp16 ctx
    attn_h<<<dim3(SEQ / 64, NH, BATCH), 128>>>(qkvh, ctx);
    // 4) output projection + residual -> fp32 src2
    gemm_h<<<dim3(D_MODEL / 128, NTOK / 128), 256, GEMM_SMEM>>>(
        ctx, woh, bo, src, src2, nullptr, NTOK, D_MODEL, D_MODEL, 0);
    // 5) LN2 -> fp16 (warp-per-row)
    ln_kernel<<<NTOK / 8, 256>>>(src2, ln2w, ln2b, xn);
    // 6) FFN up + ReLU -> fp16 ff1
    gemm_h<<<dim3(DFF / 128, NTOK / 128), 256, GEMM_SMEM>>>(
        xn, w1h, b1, nullptr, nullptr, ff1, NTOK, DFF, D_MODEL, 1);
    // 7) FFN down + residual -> fp32 out
    gemm_h<<<dim3(D_MODEL / 128, NTOK / 128), 256, GEMM_SMEM>>>(
        ff1, w2h, b2, src2, out, nullptr, NTOK, D_MODEL, DFF, 0);
}